// round 5
// baseline (speedup 1.0000x reference)
#include <cuda_runtime.h>
#include <cuda_bf16.h>
#include <cstdint>

// Problem constants (fixed shapes)
#define NN 50000
#define EE 1600000
#define IN_DIM 256
#define HC 128          // H*C = 4*32
#define OUT_DIM 64
#define NEG_SLOPE 0.2f
#define SCAN_NBLK 49    // ceil(50000/1024)

// ---------------- scratch (__device__ globals; no allocation allowed) -------
__device__ float g_h[(size_t)NN * HC];     // x @ W
__device__ float g_asrc[NN * 4];
__device__ float g_adst[NN * 4];
__device__ float g_z[(size_t)NN * HC];     // elu(agg + bias)
__device__ int   g_cnt[NN];
__device__ int   g_cur[NN];
__device__ int   g_off[NN + 1];
__device__ int   g_bsum[64];
__device__ int   g_srcsorted[EE];
__device__ int   g_is64;                   // 1 if edge_index is int64

// ---------------- edge dtype detection ---------------------------------------
// int64 little-endian values < 2^31: odd int32 words are all zero.
// int32 data: odd words are random node ids; P(64 of them all zero) ~ 0.
__global__ void detect_kernel(const int* __restrict__ ei32)
{
    if (threadIdx.x == 0 && blockIdx.x == 0) {
        int any = 0;
        for (int i = 0; i < 64; ++i) any |= ei32[2 * i + 1];
        g_is64 = (any == 0) ? 1 : 0;
    }
}

__device__ __forceinline__ int load_edge(const void* ei, size_t idx)
{
    if (g_is64) return (int)((const long long*)ei)[idx];
    return ((const int*)ei)[idx];
}

// ---------------- GEMM1: h = x @ W  (50000x256 * 256x128) -------------------
// BM=64, BN=128, BK=32, 256 threads, 8x4 per thread
__global__ void gemm1_kernel(const float* __restrict__ x,
                             const float* __restrict__ W)
{
    __shared__ float As[32][64];    // [k][m]
    __shared__ float Bs[32][128];   // [k][n]
    const int tid = threadIdx.x;
    const int tx = tid & 31;        // col group -> cols tx*4 .. tx*4+3
    const int ty = tid >> 5;        // row group -> rows ty*8 .. ty*8+7
    const int bm = blockIdx.x * 64;

    float acc[8][4];
#pragma unroll
    for (int i = 0; i < 8; ++i)
#pragma unroll
        for (int j = 0; j < 4; ++j) acc[i][j] = 0.f;

    for (int k0 = 0; k0 < IN_DIM; k0 += 32) {
        // x tile: 64 rows x 32 k = 512 float4, 2 per thread
#pragma unroll
        for (int r = 0; r < 2; ++r) {
            int idx = tid + r * 256;          // 0..511
            int row = idx >> 3;               // 0..63
            int kk4 = idx & 7;                // float4 slot in 32
            int gm = bm + row;
            float4 v = make_float4(0.f, 0.f, 0.f, 0.f);
            if (gm < NN)
                v = *reinterpret_cast<const float4*>(x + (size_t)gm * IN_DIM + k0 + kk4 * 4);
            As[kk4 * 4 + 0][row] = v.x;
            As[kk4 * 4 + 1][row] = v.y;
            As[kk4 * 4 + 2][row] = v.z;
            As[kk4 * 4 + 3][row] = v.w;
        }
        // W tile: 32 k x 128 n = 1024 float4, 4 per thread
#pragma unroll
        for (int r = 0; r < 4; ++r) {
            int idx = tid + r * 256;          // 0..1023
            int kk = idx >> 5;                // 0..31
            int nn4 = idx & 31;               // 0..31
            *reinterpret_cast<float4*>(&Bs[kk][nn4 * 4]) =
                *reinterpret_cast<const float4*>(W + (size_t)(k0 + kk) * HC + nn4 * 4);
        }
        __syncthreads();
#pragma unroll
        for (int k = 0; k < 32; ++k) {
            float4 a0 = reinterpret_cast<const float4*>(&As[k][0])[ty * 2 + 0];
            float4 a1 = reinterpret_cast<const float4*>(&As[k][0])[ty * 2 + 1];
            float4 bv = reinterpret_cast<const float4*>(&Bs[k][0])[tx];
            float a[8] = {a0.x, a0.y, a0.z, a0.w, a1.x, a1.y, a1.z, a1.w};
            float b[4] = {bv.x, bv.y, bv.z, bv.w};
#pragma unroll
            for (int i = 0; i < 8; ++i)
#pragma unroll
                for (int j = 0; j < 4; ++j) acc[i][j] = fmaf(a[i], b[j], acc[i][j]);
        }
        __syncthreads();
    }
#pragma unroll
    for (int i = 0; i < 8; ++i) {
        int gm = bm + ty * 8 + i;
        if (gm < NN) {
            *reinterpret_cast<float4*>(g_h + (size_t)gm * HC + tx * 4) =
                make_float4(acc[i][0], acc[i][1], acc[i][2], acc[i][3]);
        }
    }
}

// ---------------- attention halves: a_src/a_dst [N,4] ------------------------
__global__ void attn_halves_kernel(const float* __restrict__ att_src,
                                   const float* __restrict__ att_dst)
{
    int w = (blockIdx.x * blockDim.x + threadIdx.x) >> 5;
    int lane = threadIdx.x & 31;
    if (w >= NN) return;
    float ps[4], pd[4];
#pragma unroll
    for (int k = 0; k < 4; ++k) {
        float hv = g_h[(size_t)w * HC + k * 32 + lane];
        ps[k] = hv * att_src[k * 32 + lane];
        pd[k] = hv * att_dst[k * 32 + lane];
    }
#pragma unroll
    for (int off = 16; off; off >>= 1) {
#pragma unroll
        for (int k = 0; k < 4; ++k) {
            ps[k] += __shfl_xor_sync(0xFFFFFFFFu, ps[k], off);
            pd[k] += __shfl_xor_sync(0xFFFFFFFFu, pd[k], off);
        }
    }
    if (lane == 0) {
        *reinterpret_cast<float4*>(g_asrc + w * 4) = make_float4(ps[0], ps[1], ps[2], ps[3]);
        *reinterpret_cast<float4*>(g_adst + w * 4) = make_float4(pd[0], pd[1], pd[2], pd[3]);
    }
}

// ---------------- CSR build --------------------------------------------------
__global__ void zero_kernel()
{
    int i = blockIdx.x * blockDim.x + threadIdx.x;
    if (i < NN) { g_cnt[i] = 0; g_cur[i] = 0; }
}

__global__ void hist_kernel(const void* __restrict__ ei)
{
    int e = blockIdx.x * blockDim.x + threadIdx.x;
    if (e < EE) {
        int d = load_edge(ei, (size_t)EE + e);
        if ((unsigned)d < NN) atomicAdd(&g_cnt[d], 1);
    }
}

__global__ void scan1_kernel()
{
    __shared__ int sh[1024];
    int i = blockIdx.x * 1024 + threadIdx.x;
    int v = (i < NN) ? g_cnt[i] : 0;
    sh[threadIdx.x] = v;
    __syncthreads();
#pragma unroll
    for (int off = 1; off < 1024; off <<= 1) {
        int t = (threadIdx.x >= off) ? sh[threadIdx.x - off] : 0;
        __syncthreads();
        sh[threadIdx.x] += t;
        __syncthreads();
    }
    if (i < NN) g_off[i + 1] = sh[threadIdx.x];
    if (threadIdx.x == 1023) g_bsum[blockIdx.x] = sh[1023];
}

__global__ void scan2_kernel()
{
    if (threadIdx.x == 0) {
        int acc = 0;
        for (int b = 0; b < SCAN_NBLK; ++b) {
            int v = g_bsum[b];
            g_bsum[b] = acc;
            acc += v;
        }
    }
}

__global__ void scan3_kernel()
{
    int i = blockIdx.x * 1024 + threadIdx.x;
    if (i < NN) g_off[i + 1] += g_bsum[blockIdx.x];
    if (i == 0) g_off[0] = 0;
}

__global__ void scatter_kernel(const void* __restrict__ ei)
{
    int e = blockIdx.x * blockDim.x + threadIdx.x;
    if (e < EE) {
        int d = load_edge(ei, (size_t)EE + e);
        int s = load_edge(ei, (size_t)e);
        if ((unsigned)d < NN && (unsigned)s < NN) {
            int pos = g_off[d] + atomicAdd(&g_cur[d], 1);
            if ((unsigned)pos < EE) g_srcsorted[pos] = s;
        }
    }
}

// ---------------- aggregation: online softmax, warp per dst node -------------
__global__ void agg_kernel(const float* __restrict__ bias)
{
    int w = (blockIdx.x * blockDim.x + threadIdx.x) >> 5;
    int lane = threadIdx.x & 31;
    if (w >= NN) return;

    float4 adv4 = *reinterpret_cast<const float4*>(g_adst + w * 4);
    float4 asv4 = *reinterpret_cast<const float4*>(g_asrc + w * 4);
    float adv[4] = {adv4.x, adv4.y, adv4.z, adv4.w};
    float asl[4] = {asv4.x, asv4.y, asv4.z, asv4.w};

    float m[4], dnm[4], acc[4];
#pragma unroll
    for (int k = 0; k < 4; ++k) {
        float e = asl[k] + adv[k];
        e = (e > 0.f) ? e : NEG_SLOPE * e;   // self-loop logit
        m[k] = e;
        dnm[k] = 1.f;
        acc[k] = g_h[(size_t)w * HC + k * 32 + lane];  // p = 1
    }

    int beg = g_off[w];
    int end = g_off[w + 1];
    for (int p = beg; p < end; ++p) {
        int s = g_srcsorted[p];
        float4 a4 = __ldg(reinterpret_cast<const float4*>(g_asrc + s * 4));
        float as2[4] = {a4.x, a4.y, a4.z, a4.w};
        const float* hr = g_h + (size_t)s * HC;
        float hv[4];
#pragma unroll
        for (int k = 0; k < 4; ++k) hv[k] = __ldg(hr + k * 32 + lane);
#pragma unroll
        for (int k = 0; k < 4; ++k) {
            float e = as2[k] + adv[k];
            e = (e > 0.f) ? e : NEG_SLOPE * e;
            float nm = fmaxf(m[k], e);
            float sc = __expf(m[k] - nm);
            float pe = __expf(e - nm);
            m[k] = nm;
            dnm[k] = dnm[k] * sc + pe;
            acc[k] = acc[k] * sc + pe * hv[k];
        }
    }

#pragma unroll
    for (int k = 0; k < 4; ++k) {
        float r = acc[k] / dnm[k] + bias[k * 32 + lane];
        r = (r > 0.f) ? r : (expf(r) - 1.f);   // ELU
        g_z[(size_t)w * HC + k * 32 + lane] = r;
    }
}

// ---------------- GEMM2: out = z @ lin_W + lin_b  (50000x128 * 128x64) -------
// BM=64, BN=64, BK=32, 256 threads, 4x4 per thread
__global__ void gemm2_kernel(const float* __restrict__ linW,
                             const float* __restrict__ linb,
                             float* __restrict__ out)
{
    __shared__ float As[32][64];    // [k][m]
    __shared__ float Bs[32][64];    // [k][n]
    const int tid = threadIdx.x;
    const int tx = tid & 15;        // cols tx*4 .. tx*4+3
    const int ty = tid >> 4;        // rows ty*4 .. ty*4+3
    const int bm = blockIdx.x * 64;

    float acc[4][4];
#pragma unroll
    for (int i = 0; i < 4; ++i)
#pragma unroll
        for (int j = 0; j < 4; ++j) acc[i][j] = 0.f;

    for (int k0 = 0; k0 < HC; k0 += 32) {
        // z tile: 64 x 32 = 512 float4, 2 per thread
#pragma unroll
        for (int r = 0; r < 2; ++r) {
            int idx = tid + r * 256;
            int row = idx >> 3;
            int kk4 = idx & 7;
            int gm = bm + row;
            float4 v = make_float4(0.f, 0.f, 0.f, 0.f);
            if (gm < NN)
                v = *reinterpret_cast<const float4*>(g_z + (size_t)gm * HC + k0 + kk4 * 4);
            As[kk4 * 4 + 0][row] = v.x;
            As[kk4 * 4 + 1][row] = v.y;
            As[kk4 * 4 + 2][row] = v.z;
            As[kk4 * 4 + 3][row] = v.w;
        }
        // linW tile: 32 x 64 = 512 float4, 2 per thread
#pragma unroll
        for (int r = 0; r < 2; ++r) {
            int idx = tid + r * 256;
            int kk = idx >> 4;
            int nn4 = idx & 15;
            *reinterpret_cast<float4*>(&Bs[kk][nn4 * 4]) =
                *reinterpret_cast<const float4*>(linW + (size_t)(k0 + kk) * OUT_DIM + nn4 * 4);
        }
        __syncthreads();
#pragma unroll
        for (int k = 0; k < 32; ++k) {
            float4 av = reinterpret_cast<const float4*>(&As[k][0])[ty];
            float4 bv = reinterpret_cast<const float4*>(&Bs[k][0])[tx];
            float a[4] = {av.x, av.y, av.z, av.w};
            float b[4] = {bv.x, bv.y, bv.z, bv.w};
#pragma unroll
            for (int i = 0; i < 4; ++i)
#pragma unroll
                for (int j = 0; j < 4; ++j) acc[i][j] = fmaf(a[i], b[j], acc[i][j]);
        }
        __syncthreads();
    }
    float4 bb = *reinterpret_cast<const float4*>(linb + tx * 4);
#pragma unroll
    for (int i = 0; i < 4; ++i) {
        int gm = bm + ty * 4 + i;
        if (gm < NN) {
            *reinterpret_cast<float4*>(out + (size_t)gm * OUT_DIM + tx * 4) =
                make_float4(acc[i][0] + bb.x, acc[i][1] + bb.y,
                            acc[i][2] + bb.z, acc[i][3] + bb.w);
        }
    }
}

// ---------------- launch ------------------------------------------------------
extern "C" void kernel_launch(void* const* d_in, const int* in_sizes, int n_in,
                              void* d_out, int out_size)
{
    const float* x        = (const float*)d_in[0];
    const void*  ei       = (const void*)d_in[1];
    const float* W        = (const float*)d_in[2];
    const float* att_src  = (const float*)d_in[3];
    const float* att_dst  = (const float*)d_in[4];
    const float* bias     = (const float*)d_in[5];
    const float* lin_W    = (const float*)d_in[6];
    const float* lin_b    = (const float*)d_in[7];
    float* out            = (float*)d_out;

    const int gemm_blocks = (NN + 63) / 64;          // 782
    const int warp_blocks = (NN * 32 + 255) / 256;   // 6250
    const int edge_blocks = (EE + 255) / 256;        // 6250
    const int node_blocks = (NN + 255) / 256;        // 196

    detect_kernel<<<1, 32>>>((const int*)ei);
    gemm1_kernel<<<gemm_blocks, 256>>>(x, W);
    attn_halves_kernel<<<warp_blocks, 256>>>(att_src, att_dst);
    zero_kernel<<<node_blocks, 256>>>();
    hist_kernel<<<edge_blocks, 256>>>(ei);
    scan1_kernel<<<SCAN_NBLK, 1024>>>();
    scan2_kernel<<<1, 32>>>();
    scan3_kernel<<<SCAN_NBLK, 1024>>>();
    scatter_kernel<<<edge_blocks, 256>>>(ei);
    agg_kernel<<<warp_blocks, 256>>>(bias);
    gemm2_kernel<<<gemm_blocks, 256>>>(lin_W, lin_b, out);
}

// round 6
// speedup vs baseline: 1.2674x; 1.2674x over previous
#include <cuda_runtime.h>
#include <cuda_bf16.h>
#include <cstdint>

// Problem constants (fixed shapes)
#define NN 50000
#define EE 1600000
#define IN_DIM 256
#define HC 128          // H*C = 4*32
#define OUT_DIM 64
#define NEG_SLOPE 0.2f
#define SCAN_NBLK 49    // ceil(50000/1024)

// ---------------- scratch (__device__ globals; no allocation allowed) -------
__device__ float g_h[(size_t)NN * HC];     // x @ W
__device__ float g_asrc[NN * 4];
__device__ float g_adst[NN * 4];
__device__ float g_z[(size_t)NN * HC];     // elu(agg + bias)
__device__ int   g_cnt[NN];
__device__ int   g_cur[NN];
__device__ int   g_off[NN + 1];
__device__ int   g_bsum[64];
__device__ int   g_srcsorted[EE];
__device__ int   g_is64;                   // 1 if edge_index is int64

// ---------------- f32x2 packed FMA helpers (sm_103a FFMA2) -------------------
__device__ __forceinline__ unsigned long long pack2(float lo, float hi)
{
    unsigned long long r;
    asm("mov.b64 %0, {%1, %2};" : "=l"(r) : "f"(lo), "f"(hi));
    return r;
}
__device__ __forceinline__ void unpack2(unsigned long long v, float& lo, float& hi)
{
    asm("mov.b64 {%0, %1}, %2;" : "=f"(lo), "=f"(hi) : "l"(v));
}
__device__ __forceinline__ unsigned long long ffma2(unsigned long long a,
                                                    unsigned long long b,
                                                    unsigned long long c)
{
    unsigned long long d;
    asm("fma.rn.f32x2 %0, %1, %2, %3;" : "=l"(d) : "l"(a), "l"(b), "l"(c));
    return d;
}

// ---------------- edge dtype detection ---------------------------------------
__global__ void detect_kernel(const int* __restrict__ ei32)
{
    if (threadIdx.x == 0 && blockIdx.x == 0) {
        int any = 0;
        for (int i = 0; i < 64; ++i) any |= ei32[2 * i + 1];
        g_is64 = (any == 0) ? 1 : 0;
    }
}

__device__ __forceinline__ int load_edge(const void* ei, size_t idx)
{
    if (g_is64) return (int)((const long long*)ei)[idx];
    return ((const int*)ei)[idx];
}

// ---------------- GEMM1: h = x @ W  (50000x256 * 256x128) -------------------
// BM=64, BN=128, BK=32, 256 threads, 8x4 per thread, FFMA2 inner product
__global__ void gemm1_kernel(const float* __restrict__ x,
                             const float* __restrict__ W)
{
    __shared__ float As[32][64];    // [k][m]
    __shared__ float Bs[32][128];   // [k][n]
    const int tid = threadIdx.x;
    const int tx = tid & 31;        // cols tx*4 .. tx*4+3
    const int ty = tid >> 5;        // rows ty*8 .. ty*8+7
    const int bm = blockIdx.x * 64;

    unsigned long long acc2[8][2];
#pragma unroll
    for (int i = 0; i < 8; ++i) { acc2[i][0] = 0ull; acc2[i][1] = 0ull; }

    for (int k0 = 0; k0 < IN_DIM; k0 += 32) {
#pragma unroll
        for (int r = 0; r < 2; ++r) {
            int idx = tid + r * 256;
            int row = idx >> 3;
            int kk4 = idx & 7;
            int gm = bm + row;
            float4 v = make_float4(0.f, 0.f, 0.f, 0.f);
            if (gm < NN)
                v = *reinterpret_cast<const float4*>(x + (size_t)gm * IN_DIM + k0 + kk4 * 4);
            As[kk4 * 4 + 0][row] = v.x;
            As[kk4 * 4 + 1][row] = v.y;
            As[kk4 * 4 + 2][row] = v.z;
            As[kk4 * 4 + 3][row] = v.w;
        }
#pragma unroll
        for (int r = 0; r < 4; ++r) {
            int idx = tid + r * 256;
            int kk = idx >> 5;
            int nn4 = idx & 31;
            *reinterpret_cast<float4*>(&Bs[kk][nn4 * 4]) =
                *reinterpret_cast<const float4*>(W + (size_t)(k0 + kk) * HC + nn4 * 4);
        }
        __syncthreads();
#pragma unroll
        for (int k = 0; k < 32; ++k) {
            float4 a0 = reinterpret_cast<const float4*>(&As[k][0])[ty * 2 + 0];
            float4 a1 = reinterpret_cast<const float4*>(&As[k][0])[ty * 2 + 1];
            float4 bv = reinterpret_cast<const float4*>(&Bs[k][0])[tx];
            unsigned long long b01 = pack2(bv.x, bv.y);
            unsigned long long b23 = pack2(bv.z, bv.w);
            float a[8] = {a0.x, a0.y, a0.z, a0.w, a1.x, a1.y, a1.z, a1.w};
#pragma unroll
            for (int i = 0; i < 8; ++i) {
                unsigned long long ai = pack2(a[i], a[i]);
                acc2[i][0] = ffma2(ai, b01, acc2[i][0]);
                acc2[i][1] = ffma2(ai, b23, acc2[i][1]);
            }
        }
        __syncthreads();
    }
#pragma unroll
    for (int i = 0; i < 8; ++i) {
        int gm = bm + ty * 8 + i;
        if (gm < NN) {
            float4 o;
            unpack2(acc2[i][0], o.x, o.y);
            unpack2(acc2[i][1], o.z, o.w);
            *reinterpret_cast<float4*>(g_h + (size_t)gm * HC + tx * 4) = o;
        }
    }
}

// ---------------- attention halves: a_src/a_dst [N,4] ------------------------
__global__ void attn_halves_kernel(const float* __restrict__ att_src,
                                   const float* __restrict__ att_dst)
{
    int w = (blockIdx.x * blockDim.x + threadIdx.x) >> 5;
    int lane = threadIdx.x & 31;
    if (w >= NN) return;
    float ps[4], pd[4];
#pragma unroll
    for (int k = 0; k < 4; ++k) {
        float hv = g_h[(size_t)w * HC + k * 32 + lane];
        ps[k] = hv * att_src[k * 32 + lane];
        pd[k] = hv * att_dst[k * 32 + lane];
    }
#pragma unroll
    for (int off = 16; off; off >>= 1) {
#pragma unroll
        for (int k = 0; k < 4; ++k) {
            ps[k] += __shfl_xor_sync(0xFFFFFFFFu, ps[k], off);
            pd[k] += __shfl_xor_sync(0xFFFFFFFFu, pd[k], off);
        }
    }
    if (lane == 0) {
        *reinterpret_cast<float4*>(g_asrc + w * 4) = make_float4(ps[0], ps[1], ps[2], ps[3]);
        *reinterpret_cast<float4*>(g_adst + w * 4) = make_float4(pd[0], pd[1], pd[2], pd[3]);
    }
}

// ---------------- CSR build --------------------------------------------------
__global__ void zero_kernel()
{
    int i = blockIdx.x * blockDim.x + threadIdx.x;
    if (i < NN) { g_cnt[i] = 0; g_cur[i] = 0; }
}

__global__ void hist_kernel(const void* __restrict__ ei)
{
    int e = blockIdx.x * blockDim.x + threadIdx.x;
    if (e < EE) {
        int d = load_edge(ei, (size_t)EE + e);
        if ((unsigned)d < NN) atomicAdd(&g_cnt[d], 1);
    }
}

__global__ void scan1_kernel()
{
    __shared__ int sh[1024];
    int i = blockIdx.x * 1024 + threadIdx.x;
    int v = (i < NN) ? g_cnt[i] : 0;
    sh[threadIdx.x] = v;
    __syncthreads();
#pragma unroll
    for (int off = 1; off < 1024; off <<= 1) {
        int t = (threadIdx.x >= off) ? sh[threadIdx.x - off] : 0;
        __syncthreads();
        sh[threadIdx.x] += t;
        __syncthreads();
    }
    if (i < NN) g_off[i + 1] = sh[threadIdx.x];
    if (threadIdx.x == 1023) g_bsum[blockIdx.x] = sh[1023];
}

__global__ void scan2_kernel()
{
    if (threadIdx.x == 0) {
        int acc = 0;
        for (int b = 0; b < SCAN_NBLK; ++b) {
            int v = g_bsum[b];
            g_bsum[b] = acc;
            acc += v;
        }
    }
}

__global__ void scan3_kernel()
{
    int i = blockIdx.x * 1024 + threadIdx.x;
    if (i < NN) g_off[i + 1] += g_bsum[blockIdx.x];
    if (i == 0) g_off[0] = 0;
}

__global__ void scatter_kernel(const void* __restrict__ ei)
{
    int e = blockIdx.x * blockDim.x + threadIdx.x;
    if (e < EE) {
        int d = load_edge(ei, (size_t)EE + e);
        int s = load_edge(ei, (size_t)e);
        if ((unsigned)d < NN && (unsigned)s < NN) {
            int pos = g_off[d] + atomicAdd(&g_cur[d], 1);
            if ((unsigned)pos < EE) g_srcsorted[pos] = s;
        }
    }
}

// ---------------- aggregation: warp per dst, lane-parallel exp ---------------
// Softmax without max-shift (logits bounded ~|3.5|, shift-invariant => exact).
// Lane roles for the logit phase: lane = j*4 + k  (j = edge slot 0..7, k = head).
// Lane roles for the accumulate phase: lane = channel within head.
__global__ void agg_kernel(const float* __restrict__ bias)
{
    int w = (blockIdx.x * blockDim.x + threadIdx.x) >> 5;
    int lane = threadIdx.x & 31;
    if (w >= NN) return;
    const int k = lane & 3;
    const int j = lane >> 2;

    float adv_k = g_adst[w * 4 + k];
    float asl_k = g_asrc[w * 4 + k];

    // self-loop contribution
    float e0 = asl_k + adv_k;
    e0 = (e0 > 0.f) ? e0 : NEG_SLOPE * e0;
    float pe0 = __expf(e0);
    float dnm_part = (j == 0) ? pe0 : 0.f;

    float acc[4];
#pragma unroll
    for (int k2 = 0; k2 < 4; ++k2) {
        float p0 = __shfl_sync(0xFFFFFFFFu, pe0, k2);  // lane k2 holds head k2 (j=0)
        acc[k2] = p0 * g_h[(size_t)w * HC + k2 * 32 + lane];
    }

    const int beg = g_off[w];
    const int end = g_off[w + 1];
    int p = beg;
    // full blocks of 8 edges
    for (; p + 8 <= end; p += 8) {
        int s = g_srcsorted[p + j];
        float as = __ldg(g_asrc + (size_t)s * 4 + k);
        float e = as + adv_k;
        e = (e > 0.f) ? e : NEG_SLOPE * e;
        float pe = __expf(e);
        dnm_part += pe;
#pragma unroll
        for (int jj = 0; jj < 8; ++jj) {
            int sj = __shfl_sync(0xFFFFFFFFu, s, jj * 4);
            float q0 = __shfl_sync(0xFFFFFFFFu, pe, jj * 4 + 0);
            float q1 = __shfl_sync(0xFFFFFFFFu, pe, jj * 4 + 1);
            float q2 = __shfl_sync(0xFFFFFFFFu, pe, jj * 4 + 2);
            float q3 = __shfl_sync(0xFFFFFFFFu, pe, jj * 4 + 3);
            const float* hr = g_h + (size_t)sj * HC;
            acc[0] = fmaf(q0, __ldg(hr + 0 * 32 + lane), acc[0]);
            acc[1] = fmaf(q1, __ldg(hr + 1 * 32 + lane), acc[1]);
            acc[2] = fmaf(q2, __ldg(hr + 2 * 32 + lane), acc[2]);
            acc[3] = fmaf(q3, __ldg(hr + 3 * 32 + lane), acc[3]);
        }
    }
    // tail (< 8 edges)
    if (p < end) {
        int cnt = end - p;
        int ridx = p + ((j < cnt) ? j : (cnt - 1));
        int s = g_srcsorted[ridx];
        float as = __ldg(g_asrc + (size_t)s * 4 + k);
        float e = as + adv_k;
        e = (e > 0.f) ? e : NEG_SLOPE * e;
        float pe = (j < cnt) ? __expf(e) : 0.f;
        dnm_part += pe;
        for (int jj = 0; jj < cnt; ++jj) {
            int sj = __shfl_sync(0xFFFFFFFFu, s, jj * 4);
            float q0 = __shfl_sync(0xFFFFFFFFu, pe, jj * 4 + 0);
            float q1 = __shfl_sync(0xFFFFFFFFu, pe, jj * 4 + 1);
            float q2 = __shfl_sync(0xFFFFFFFFu, pe, jj * 4 + 2);
            float q3 = __shfl_sync(0xFFFFFFFFu, pe, jj * 4 + 3);
            const float* hr = g_h + (size_t)sj * HC;
            acc[0] = fmaf(q0, __ldg(hr + 0 * 32 + lane), acc[0]);
            acc[1] = fmaf(q1, __ldg(hr + 1 * 32 + lane), acc[1]);
            acc[2] = fmaf(q2, __ldg(hr + 2 * 32 + lane), acc[2]);
            acc[3] = fmaf(q3, __ldg(hr + 3 * 32 + lane), acc[3]);
        }
    }

    // reduce dnm over the 8 edge slots (bits 2..4 of lane)
    dnm_part += __shfl_xor_sync(0xFFFFFFFFu, dnm_part, 4);
    dnm_part += __shfl_xor_sync(0xFFFFFFFFu, dnm_part, 8);
    dnm_part += __shfl_xor_sync(0xFFFFFFFFu, dnm_part, 16);
    // lane l now holds the full denom for head (l & 3)

#pragma unroll
    for (int k2 = 0; k2 < 4; ++k2) {
        float dn = __shfl_sync(0xFFFFFFFFu, dnm_part, k2);
        float r = acc[k2] / dn + bias[k2 * 32 + lane];
        r = (r > 0.f) ? r : (__expf(r) - 1.f);   // ELU
        g_z[(size_t)w * HC + k2 * 32 + lane] = r;
    }
}

// ---------------- GEMM2: out = z @ lin_W + lin_b  (50000x128 * 128x64) -------
// BM=64, BN=64, BK=32, 256 threads, 4x4 per thread, FFMA2
__global__ void gemm2_kernel(const float* __restrict__ linW,
                             const float* __restrict__ linb,
                             float* __restrict__ out)
{
    __shared__ float As[32][64];    // [k][m]
    __shared__ float Bs[32][64];    // [k][n]
    const int tid = threadIdx.x;
    const int tx = tid & 15;        // cols tx*4 .. tx*4+3
    const int ty = tid >> 4;        // rows ty*4 .. ty*4+3
    const int bm = blockIdx.x * 64;

    unsigned long long acc2[4][2];
#pragma unroll
    for (int i = 0; i < 4; ++i) { acc2[i][0] = 0ull; acc2[i][1] = 0ull; }

    for (int k0 = 0; k0 < HC; k0 += 32) {
#pragma unroll
        for (int r = 0; r < 2; ++r) {
            int idx = tid + r * 256;
            int row = idx >> 3;
            int kk4 = idx & 7;
            int gm = bm + row;
            float4 v = make_float4(0.f, 0.f, 0.f, 0.f);
            if (gm < NN)
                v = *reinterpret_cast<const float4*>(g_z + (size_t)gm * HC + k0 + kk4 * 4);
            As[kk4 * 4 + 0][row] = v.x;
            As[kk4 * 4 + 1][row] = v.y;
            As[kk4 * 4 + 2][row] = v.z;
            As[kk4 * 4 + 3][row] = v.w;
        }
#pragma unroll
        for (int r = 0; r < 2; ++r) {
            int idx = tid + r * 256;
            int kk = idx >> 4;
            int nn4 = idx & 15;
            *reinterpret_cast<float4*>(&Bs[kk][nn4 * 4]) =
                *reinterpret_cast<const float4*>(linW + (size_t)(k0 + kk) * OUT_DIM + nn4 * 4);
        }
        __syncthreads();
#pragma unroll
        for (int k = 0; k < 32; ++k) {
            float4 av = reinterpret_cast<const float4*>(&As[k][0])[ty];
            float4 bv = reinterpret_cast<const float4*>(&Bs[k][0])[tx];
            unsigned long long b01 = pack2(bv.x, bv.y);
            unsigned long long b23 = pack2(bv.z, bv.w);
            float a[4] = {av.x, av.y, av.z, av.w};
#pragma unroll
            for (int i = 0; i < 4; ++i) {
                unsigned long long ai = pack2(a[i], a[i]);
                acc2[i][0] = ffma2(ai, b01, acc2[i][0]);
                acc2[i][1] = ffma2(ai, b23, acc2[i][1]);
            }
        }
        __syncthreads();
    }
    float4 bb = *reinterpret_cast<const float4*>(linb + tx * 4);
#pragma unroll
    for (int i = 0; i < 4; ++i) {
        int gm = bm + ty * 4 + i;
        if (gm < NN) {
            float4 o;
            unpack2(acc2[i][0], o.x, o.y);
            unpack2(acc2[i][1], o.z, o.w);
            o.x += bb.x; o.y += bb.y; o.z += bb.z; o.w += bb.w;
            *reinterpret_cast<float4*>(out + (size_t)gm * OUT_DIM + tx * 4) = o;
        }
    }
}

// ---------------- launch ------------------------------------------------------
extern "C" void kernel_launch(void* const* d_in, const int* in_sizes, int n_in,
                              void* d_out, int out_size)
{
    const float* x        = (const float*)d_in[0];
    const void*  ei       = (const void*)d_in[1];
    const float* W        = (const float*)d_in[2];
    const float* att_src  = (const float*)d_in[3];
    const float* att_dst  = (const float*)d_in[4];
    const float* bias     = (const float*)d_in[5];
    const float* lin_W    = (const float*)d_in[6];
    const float* lin_b    = (const float*)d_in[7];
    float* out            = (float*)d_out;

    const int gemm_blocks = (NN + 63) / 64;          // 782
    const int warp_blocks = (NN * 32 + 255) / 256;   // 6250
    const int edge_blocks = (EE + 255) / 256;        // 6250
    const int node_blocks = (NN + 255) / 256;        // 196

    detect_kernel<<<1, 32>>>((const int*)ei);
    gemm1_kernel<<<gemm_blocks, 256>>>(x, W);
    attn_halves_kernel<<<warp_blocks, 256>>>(att_src, att_dst);
    zero_kernel<<<node_blocks, 256>>>();
    hist_kernel<<<edge_blocks, 256>>>(ei);
    scan1_kernel<<<SCAN_NBLK, 1024>>>();
    scan2_kernel<<<1, 32>>>();
    scan3_kernel<<<SCAN_NBLK, 1024>>>();
    scatter_kernel<<<edge_blocks, 256>>>(ei);
    agg_kernel<<<warp_blocks, 256>>>(bias);
    gemm2_kernel<<<gemm_blocks, 256>>>(lin_W, lin_b, out);
}

// round 7
// speedup vs baseline: 1.3879x; 1.0950x over previous
#include <cuda_runtime.h>
#include <cuda_bf16.h>
#include <cstdint>

// Problem constants (fixed shapes)
#define NN 50000
#define EE 1600000
#define IN_DIM 256
#define HC 128          // H*C = 4*32
#define OUT_DIM 64
#define NEG_SLOPE 0.2f
#define SCAN_NBLK 49    // ceil(50000/1024)

// ---------------- scratch (__device__ globals; no allocation allowed) -------
__device__ float g_h[(size_t)NN * HC];     // x @ W
__device__ float g_asrc[NN * 4];
__device__ float g_adst[NN * 4];
__device__ float g_z[(size_t)NN * HC];     // elu(agg + bias)
__device__ int   g_cnt[NN];
__device__ int   g_cur[NN];
__device__ int   g_off[NN + 1];
__device__ int   g_bsum[64];
__device__ int   g_srcsorted[EE];
__device__ int   g_is64;                   // 1 if edge_index is int64

// ---------------- f32x2 packed FMA helpers (sm_103a FFMA2) -------------------
__device__ __forceinline__ unsigned long long pack2(float lo, float hi)
{
    unsigned long long r;
    asm("mov.b64 %0, {%1, %2};" : "=l"(r) : "f"(lo), "f"(hi));
    return r;
}
__device__ __forceinline__ void unpack2(unsigned long long v, float& lo, float& hi)
{
    asm("mov.b64 {%0, %1}, %2;" : "=f"(lo), "=f"(hi) : "l"(v));
}
__device__ __forceinline__ unsigned long long ffma2(unsigned long long a,
                                                    unsigned long long b,
                                                    unsigned long long c)
{
    unsigned long long d;
    asm("fma.rn.f32x2 %0, %1, %2, %3;" : "=l"(d) : "l"(a), "l"(b), "l"(c));
    return d;
}

// ---------------- edge dtype detection ---------------------------------------
__global__ void detect_kernel(const int* __restrict__ ei32)
{
    if (threadIdx.x == 0 && blockIdx.x == 0) {
        int any = 0;
        for (int i = 0; i < 64; ++i) any |= ei32[2 * i + 1];
        g_is64 = (any == 0) ? 1 : 0;
    }
}

__device__ __forceinline__ int load_edge(const void* ei, size_t idx)
{
    if (g_is64) return (int)((const long long*)ei)[idx];
    return ((const int*)ei)[idx];
}

// ---------------- GEMM1: h = x @ W  (50000x256 * 256x128) -------------------
// BM=64, BN=128, BK=32, 256 threads, 8x4 per thread, FFMA2 inner product
__global__ void gemm1_kernel(const float* __restrict__ x,
                             const float* __restrict__ W)
{
    __shared__ float As[32][64];    // [k][m]
    __shared__ float Bs[32][128];   // [k][n]
    const int tid = threadIdx.x;
    const int tx = tid & 31;        // cols tx*4 .. tx*4+3
    const int ty = tid >> 5;        // rows ty*8 .. ty*8+7
    const int bm = blockIdx.x * 64;

    unsigned long long acc2[8][2];
#pragma unroll
    for (int i = 0; i < 8; ++i) { acc2[i][0] = 0ull; acc2[i][1] = 0ull; }

    for (int k0 = 0; k0 < IN_DIM; k0 += 32) {
#pragma unroll
        for (int r = 0; r < 2; ++r) {
            int idx = tid + r * 256;
            int row = idx >> 3;
            int kk4 = idx & 7;
            int gm = bm + row;
            float4 v = make_float4(0.f, 0.f, 0.f, 0.f);
            if (gm < NN)
                v = *reinterpret_cast<const float4*>(x + (size_t)gm * IN_DIM + k0 + kk4 * 4);
            As[kk4 * 4 + 0][row] = v.x;
            As[kk4 * 4 + 1][row] = v.y;
            As[kk4 * 4 + 2][row] = v.z;
            As[kk4 * 4 + 3][row] = v.w;
        }
#pragma unroll
        for (int r = 0; r < 4; ++r) {
            int idx = tid + r * 256;
            int kk = idx >> 5;
            int nn4 = idx & 31;
            *reinterpret_cast<float4*>(&Bs[kk][nn4 * 4]) =
                *reinterpret_cast<const float4*>(W + (size_t)(k0 + kk) * HC + nn4 * 4);
        }
        __syncthreads();
#pragma unroll
        for (int k = 0; k < 32; ++k) {
            float4 a0 = reinterpret_cast<const float4*>(&As[k][0])[ty * 2 + 0];
            float4 a1 = reinterpret_cast<const float4*>(&As[k][0])[ty * 2 + 1];
            float4 bv = reinterpret_cast<const float4*>(&Bs[k][0])[tx];
            unsigned long long b01 = pack2(bv.x, bv.y);
            unsigned long long b23 = pack2(bv.z, bv.w);
            float a[8] = {a0.x, a0.y, a0.z, a0.w, a1.x, a1.y, a1.z, a1.w};
#pragma unroll
            for (int i = 0; i < 8; ++i) {
                unsigned long long ai = pack2(a[i], a[i]);
                acc2[i][0] = ffma2(ai, b01, acc2[i][0]);
                acc2[i][1] = ffma2(ai, b23, acc2[i][1]);
            }
        }
        __syncthreads();
    }
#pragma unroll
    for (int i = 0; i < 8; ++i) {
        int gm = bm + ty * 8 + i;
        if (gm < NN) {
            float4 o;
            unpack2(acc2[i][0], o.x, o.y);
            unpack2(acc2[i][1], o.z, o.w);
            *reinterpret_cast<float4*>(g_h + (size_t)gm * HC + tx * 4) = o;
        }
    }
}

// ---------------- attention halves: a_src/a_dst [N,4] ------------------------
// lane owns channels lane*4..lane*4+3, head = lane>>3; 8-lane group reduction
__global__ void attn_halves_kernel(const float* __restrict__ att_src,
                                   const float* __restrict__ att_dst)
{
    int w = (blockIdx.x * blockDim.x + threadIdx.x) >> 5;
    int lane = threadIdx.x & 31;
    if (w >= NN) return;
    float4 hv = *reinterpret_cast<const float4*>(g_h + (size_t)w * HC + lane * 4);
    float4 s4 = *reinterpret_cast<const float4*>(att_src + lane * 4);
    float4 d4 = *reinterpret_cast<const float4*>(att_dst + lane * 4);
    float ps = hv.x * s4.x + hv.y * s4.y + hv.z * s4.z + hv.w * s4.w;
    float pd = hv.x * d4.x + hv.y * d4.y + hv.z * d4.z + hv.w * d4.w;
#pragma unroll
    for (int off = 1; off < 8; off <<= 1) {
        ps += __shfl_xor_sync(0xFFFFFFFFu, ps, off);
        pd += __shfl_xor_sync(0xFFFFFFFFu, pd, off);
    }
    // lanes 0,8,16,24 hold head sums
    float4 po, qo;
    po.x = __shfl_sync(0xFFFFFFFFu, ps, 0);
    po.y = __shfl_sync(0xFFFFFFFFu, ps, 8);
    po.z = __shfl_sync(0xFFFFFFFFu, ps, 16);
    po.w = __shfl_sync(0xFFFFFFFFu, ps, 24);
    qo.x = __shfl_sync(0xFFFFFFFFu, pd, 0);
    qo.y = __shfl_sync(0xFFFFFFFFu, pd, 8);
    qo.z = __shfl_sync(0xFFFFFFFFu, pd, 16);
    qo.w = __shfl_sync(0xFFFFFFFFu, pd, 24);
    if (lane == 0) {
        *reinterpret_cast<float4*>(g_asrc + w * 4) = po;
        *reinterpret_cast<float4*>(g_adst + w * 4) = qo;
    }
}

// ---------------- CSR build --------------------------------------------------
__global__ void hist_kernel(const void* __restrict__ ei)
{
    int e = blockIdx.x * blockDim.x + threadIdx.x;
    if (e < EE) {
        int d = load_edge(ei, (size_t)EE + e);
        if ((unsigned)d < NN) atomicAdd(&g_cnt[d], 1);
    }
}

__global__ void scan1_kernel()
{
    __shared__ int sh[1024];
    int i = blockIdx.x * 1024 + threadIdx.x;
    int v = (i < NN) ? g_cnt[i] : 0;
    sh[threadIdx.x] = v;
    __syncthreads();
#pragma unroll
    for (int off = 1; off < 1024; off <<= 1) {
        int t = (threadIdx.x >= off) ? sh[threadIdx.x - off] : 0;
        __syncthreads();
        sh[threadIdx.x] += t;
        __syncthreads();
    }
    if (i < NN) g_off[i + 1] = sh[threadIdx.x];
    if (threadIdx.x == 1023) g_bsum[blockIdx.x] = sh[1023];
}

__global__ void scan2_kernel()
{
    if (threadIdx.x == 0) {
        int acc = 0;
        for (int b = 0; b < SCAN_NBLK; ++b) {
            int v = g_bsum[b];
            g_bsum[b] = acc;
            acc += v;
        }
    }
}

__global__ void scan3_kernel()
{
    int i = blockIdx.x * 1024 + threadIdx.x;
    if (i < NN) g_off[i + 1] += g_bsum[blockIdx.x];
    if (i == 0) g_off[0] = 0;
}

__global__ void scatter_kernel(const void* __restrict__ ei)
{
    int e = blockIdx.x * blockDim.x + threadIdx.x;
    if (e < EE) {
        int d = load_edge(ei, (size_t)EE + e);
        int s = load_edge(ei, (size_t)e);
        if ((unsigned)d < NN && (unsigned)s < NN) {
            int pos = g_off[d] + atomicAdd(&g_cur[d], 1);
            if ((unsigned)pos < EE) g_srcsorted[pos] = s;
        }
    }
}

// ---------------- aggregation: warp per dst node -----------------------------
// Softmax without max-shift (logits bounded, shift-invariant => exact).
// Logit role:     lane = j*4 + kl  (j = edge slot 0..7, kl = head)
// Accumulate role: lane owns channels lane*4..lane*4+3, head kh = lane>>3
__global__ void agg_kernel(const float* __restrict__ bias)
{
    int w = (blockIdx.x * blockDim.x + threadIdx.x) >> 5;
    int lane = threadIdx.x & 31;
    if (w >= NN) return;
    const int kl = lane & 3;
    const int j  = lane >> 2;
    const int kh = lane >> 3;

    float adv_l = g_adst[w * 4 + kl];
    float asl_l = g_asrc[w * 4 + kl];
    float adv_a = g_adst[w * 4 + kh];
    float asl_a = g_asrc[w * 4 + kh];

    // self-loop contribution
    float e0l = asl_l + adv_l;
    e0l = (e0l > 0.f) ? e0l : NEG_SLOPE * e0l;
    float dnm = (j == 0) ? __expf(e0l) : 0.f;

    float e0a = asl_a + adv_a;
    e0a = (e0a > 0.f) ? e0a : NEG_SLOPE * e0a;
    float pe0a = __expf(e0a);
    float4 hw = *reinterpret_cast<const float4*>(g_h + (size_t)w * HC + lane * 4);
    float4 acc;
    acc.x = pe0a * hw.x; acc.y = pe0a * hw.y;
    acc.z = pe0a * hw.z; acc.w = pe0a * hw.w;

    const int beg = g_off[w];
    const int end = g_off[w + 1];
    int p = beg;
    for (; p + 8 <= end; p += 8) {
        int s = g_srcsorted[p + j];
        float as = __ldg(g_asrc + (size_t)s * 4 + kl);
        float e = as + adv_l;
        e = (e > 0.f) ? e : NEG_SLOPE * e;
        float pe = __expf(e);
        dnm += pe;
#pragma unroll
        for (int jj = 0; jj < 8; ++jj) {
            int   sj = __shfl_sync(0xFFFFFFFFu, s,  jj * 4);
            float q  = __shfl_sync(0xFFFFFFFFu, pe, jj * 4 + kh);
            float4 hv = __ldg(reinterpret_cast<const float4*>(g_h + (size_t)sj * HC) + lane);
            acc.x = fmaf(q, hv.x, acc.x);
            acc.y = fmaf(q, hv.y, acc.y);
            acc.z = fmaf(q, hv.z, acc.z);
            acc.w = fmaf(q, hv.w, acc.w);
        }
    }
    if (p < end) {
        int cnt = end - p;
        int ridx = p + ((j < cnt) ? j : (cnt - 1));
        int s = g_srcsorted[ridx];
        float as = __ldg(g_asrc + (size_t)s * 4 + kl);
        float e = as + adv_l;
        e = (e > 0.f) ? e : NEG_SLOPE * e;
        float pe = (j < cnt) ? __expf(e) : 0.f;
        dnm += pe;
        for (int jj = 0; jj < cnt; ++jj) {
            int   sj = __shfl_sync(0xFFFFFFFFu, s,  jj * 4);
            float q  = __shfl_sync(0xFFFFFFFFu, pe, jj * 4 + kh);
            float4 hv = __ldg(reinterpret_cast<const float4*>(g_h + (size_t)sj * HC) + lane);
            acc.x = fmaf(q, hv.x, acc.x);
            acc.y = fmaf(q, hv.y, acc.y);
            acc.z = fmaf(q, hv.z, acc.z);
            acc.w = fmaf(q, hv.w, acc.w);
        }
    }

    // reduce dnm over the 8 edge slots; lane l then holds denom for head (l&3)
    dnm += __shfl_xor_sync(0xFFFFFFFFu, dnm, 4);
    dnm += __shfl_xor_sync(0xFFFFFFFFu, dnm, 8);
    dnm += __shfl_xor_sync(0xFFFFFFFFu, dnm, 16);
    float dn = __shfl_sync(0xFFFFFFFFu, dnm, kh);  // lanes 0..3 hold heads 0..3
    float inv = 1.f / dn;

    float4 bb = *reinterpret_cast<const float4*>(bias + lane * 4);
    float4 r;
    r.x = acc.x * inv + bb.x;
    r.y = acc.y * inv + bb.y;
    r.z = acc.z * inv + bb.z;
    r.w = acc.w * inv + bb.w;
    r.x = (r.x > 0.f) ? r.x : (__expf(r.x) - 1.f);
    r.y = (r.y > 0.f) ? r.y : (__expf(r.y) - 1.f);
    r.z = (r.z > 0.f) ? r.z : (__expf(r.z) - 1.f);
    r.w = (r.w > 0.f) ? r.w : (__expf(r.w) - 1.f);
    *reinterpret_cast<float4*>(g_z + (size_t)w * HC + lane * 4) = r;
}

// ---------------- GEMM2: out = z @ lin_W + lin_b  (50000x128 * 128x64) -------
// BM=64, BN=64, BK=32, 256 threads, 4x4 per thread, FFMA2
__global__ void gemm2_kernel(const float* __restrict__ linW,
                             const float* __restrict__ linb,
                             float* __restrict__ out)
{
    __shared__ float As[32][64];    // [k][m]
    __shared__ float Bs[32][64];    // [k][n]
    const int tid = threadIdx.x;
    const int tx = tid & 15;        // cols tx*4 .. tx*4+3
    const int ty = tid >> 4;        // rows ty*4 .. ty*4+3
    const int bm = blockIdx.x * 64;

    unsigned long long acc2[4][2];
#pragma unroll
    for (int i = 0; i < 4; ++i) { acc2[i][0] = 0ull; acc2[i][1] = 0ull; }

    for (int k0 = 0; k0 < HC; k0 += 32) {
#pragma unroll
        for (int r = 0; r < 2; ++r) {
            int idx = tid + r * 256;
            int row = idx >> 3;
            int kk4 = idx & 7;
            int gm = bm + row;
            float4 v = make_float4(0.f, 0.f, 0.f, 0.f);
            if (gm < NN)
                v = *reinterpret_cast<const float4*>(g_z + (size_t)gm * HC + k0 + kk4 * 4);
            As[kk4 * 4 + 0][row] = v.x;
            As[kk4 * 4 + 1][row] = v.y;
            As[kk4 * 4 + 2][row] = v.z;
            As[kk4 * 4 + 3][row] = v.w;
        }
#pragma unroll
        for (int r = 0; r < 2; ++r) {
            int idx = tid + r * 256;
            int kk = idx >> 4;
            int nn4 = idx & 15;
            *reinterpret_cast<float4*>(&Bs[kk][nn4 * 4]) =
                *reinterpret_cast<const float4*>(linW + (size_t)(k0 + kk) * OUT_DIM + nn4 * 4);
        }
        __syncthreads();
#pragma unroll
        for (int k = 0; k < 32; ++k) {
            float4 av = reinterpret_cast<const float4*>(&As[k][0])[ty];
            float4 bv = reinterpret_cast<const float4*>(&Bs[k][0])[tx];
            unsigned long long b01 = pack2(bv.x, bv.y);
            unsigned long long b23 = pack2(bv.z, bv.w);
            float a[4] = {av.x, av.y, av.z, av.w};
#pragma unroll
            for (int i = 0; i < 4; ++i) {
                unsigned long long ai = pack2(a[i], a[i]);
                acc2[i][0] = ffma2(ai, b01, acc2[i][0]);
                acc2[i][1] = ffma2(ai, b23, acc2[i][1]);
            }
        }
        __syncthreads();
    }
    float4 bb = *reinterpret_cast<const float4*>(linb + tx * 4);
#pragma unroll
    for (int i = 0; i < 4; ++i) {
        int gm = bm + ty * 4 + i;
        if (gm < NN) {
            float4 o;
            unpack2(acc2[i][0], o.x, o.y);
            unpack2(acc2[i][1], o.z, o.w);
            o.x += bb.x; o.y += bb.y; o.z += bb.z; o.w += bb.w;
            *reinterpret_cast<float4*>(out + (size_t)gm * OUT_DIM + tx * 4) = o;
        }
    }
}

// ---------------- launch ------------------------------------------------------
extern "C" void kernel_launch(void* const* d_in, const int* in_sizes, int n_in,
                              void* d_out, int out_size)
{
    const float* x        = (const float*)d_in[0];
    const void*  ei       = (const void*)d_in[1];
    const float* W        = (const float*)d_in[2];
    const float* att_src  = (const float*)d_in[3];
    const float* att_dst  = (const float*)d_in[4];
    const float* bias     = (const float*)d_in[5];
    const float* lin_W    = (const float*)d_in[6];
    const float* lin_b    = (const float*)d_in[7];
    float* out            = (float*)d_out;

    const int gemm_blocks = (NN + 63) / 64;          // 782
    const int warp_blocks = (NN * 32 + 255) / 256;   // 6250
    const int edge_blocks = (EE + 255) / 256;        // 6250

    void* cnt_ptr = nullptr;
    void* cur_ptr = nullptr;
    cudaGetSymbolAddress(&cnt_ptr, g_cnt);
    cudaGetSymbolAddress(&cur_ptr, g_cur);

    detect_kernel<<<1, 32>>>((const int*)ei);
    cudaMemsetAsync(cnt_ptr, 0, NN * sizeof(int));
    cudaMemsetAsync(cur_ptr, 0, NN * sizeof(int));
    hist_kernel<<<edge_blocks, 256>>>(ei);
    scan1_kernel<<<SCAN_NBLK, 1024>>>();
    scan2_kernel<<<1, 32>>>();
    scan3_kernel<<<SCAN_NBLK, 1024>>>();
    scatter_kernel<<<edge_blocks, 256>>>(ei);
    gemm1_kernel<<<gemm_blocks, 256>>>(x, W);
    attn_halves_kernel<<<warp_blocks, 256>>>(att_src, att_dst);
    agg_kernel<<<warp_blocks, 256>>>(bias);
    gemm2_kernel<<<gemm_blocks, 256>>>(lin_W, lin_b, out);
}

// round 8
// speedup vs baseline: 1.4723x; 1.0609x over previous
#include <cuda_runtime.h>
#include <cuda_bf16.h>
#include <cstdint>

// Problem constants (fixed shapes)
#define NN 50000
#define EE 1600000
#define IN_DIM 256
#define HC 128          // H*C = 4*32
#define OUT_DIM 64
#define NEG_SLOPE 0.2f
#define SCAN_NBLK 49    // ceil(50000/1024)
#define G1BLK 782       // gemm1 blocks  (ceil(50000/64))
#define HISTBLK 6250    // hist blocks   (EE/256)
#define ATTNBLK 1563    // attn blocks   (ceil(50000/32) nodes @32 warps/blk)

// ---------------- scratch (__device__ globals; no allocation allowed) -------
__device__ float g_h[(size_t)NN * HC];     // x @ W
__device__ float g_asrc[NN * 4];
__device__ float g_adst[NN * 4];
__device__ float g_z[(size_t)NN * HC];     // elu(agg + bias)
__device__ int   g_cnt[NN];
__device__ int   g_off[NN + 1];
__device__ int   g_bsum[64];
__device__ int   g_srcsorted[EE];

// ---------------- f32x2 packed FMA helpers (sm_103a FFMA2) -------------------
__device__ __forceinline__ unsigned long long pack2(float lo, float hi)
{
    unsigned long long r;
    asm("mov.b64 %0, {%1, %2};" : "=l"(r) : "f"(lo), "f"(hi));
    return r;
}
__device__ __forceinline__ void unpack2(unsigned long long v, float& lo, float& hi)
{
    asm("mov.b64 {%0, %1}, %2;" : "=f"(lo), "=f"(hi) : "l"(v));
}
__device__ __forceinline__ unsigned long long ffma2(unsigned long long a,
                                                    unsigned long long b,
                                                    unsigned long long c)
{
    unsigned long long d;
    asm("fma.rn.f32x2 %0, %1, %2, %3;" : "=l"(d) : "l"(a), "l"(b), "l"(c));
    return d;
}

// ---------------- per-block edge dtype detection ------------------------------
// int64 little-endian values < 2^31: odd int32 words are all zero.
// Each block computes this locally (needs a full block: uses __syncthreads_or).
__device__ __forceinline__ int block_detect_is64(const int* __restrict__ ei32)
{
    int any = 0;
    if (threadIdx.x < 64) any = ei32[2 * threadIdx.x + 1];
    return __syncthreads_or(any) ? 0 : 1;
}

__device__ __forceinline__ int load_edge(const void* ei, size_t idx, int is64)
{
    if (is64) return (int)((const long long*)ei)[idx];
    return ((const int*)ei)[idx];
}

// ---------------- fused1: gemm1 tiles  ||  hist -------------------------------
// blocks [0, G1BLK)         : gemm1  h = x @ W   (BM=64,BN=128,BK=32, FFMA2)
// blocks [G1BLK, G1BLK+HIST): histogram of dst
__global__ void fused1_kernel(const float* __restrict__ x,
                              const float* __restrict__ W,
                              const void* __restrict__ ei)
{
    if (blockIdx.x >= G1BLK) {
        // ---- hist path ----
        int is64 = block_detect_is64((const int*)ei);
        int e = (blockIdx.x - G1BLK) * 256 + threadIdx.x;
        if (e < EE) {
            int d = load_edge(ei, (size_t)EE + e, is64);
            if ((unsigned)d < NN) atomicAdd(&g_cnt[d], 1);
        }
        return;
    }
    // ---- gemm1 path ----
    __shared__ float As[32][64];    // [k][m]
    __shared__ float Bs[32][128];   // [k][n]
    const int tid = threadIdx.x;
    const int tx = tid & 31;
    const int ty = tid >> 5;
    const int bm = blockIdx.x * 64;

    unsigned long long acc2[8][2];
#pragma unroll
    for (int i = 0; i < 8; ++i) { acc2[i][0] = 0ull; acc2[i][1] = 0ull; }

    for (int k0 = 0; k0 < IN_DIM; k0 += 32) {
#pragma unroll
        for (int r = 0; r < 2; ++r) {
            int idx = tid + r * 256;
            int row = idx >> 3;
            int kk4 = idx & 7;
            int gm = bm + row;
            float4 v = make_float4(0.f, 0.f, 0.f, 0.f);
            if (gm < NN)
                v = *reinterpret_cast<const float4*>(x + (size_t)gm * IN_DIM + k0 + kk4 * 4);
            As[kk4 * 4 + 0][row] = v.x;
            As[kk4 * 4 + 1][row] = v.y;
            As[kk4 * 4 + 2][row] = v.z;
            As[kk4 * 4 + 3][row] = v.w;
        }
#pragma unroll
        for (int r = 0; r < 4; ++r) {
            int idx = tid + r * 256;
            int kk = idx >> 5;
            int nn4 = idx & 31;
            *reinterpret_cast<float4*>(&Bs[kk][nn4 * 4]) =
                *reinterpret_cast<const float4*>(W + (size_t)(k0 + kk) * HC + nn4 * 4);
        }
        __syncthreads();
#pragma unroll
        for (int k = 0; k < 32; ++k) {
            float4 a0 = reinterpret_cast<const float4*>(&As[k][0])[ty * 2 + 0];
            float4 a1 = reinterpret_cast<const float4*>(&As[k][0])[ty * 2 + 1];
            float4 bv = reinterpret_cast<const float4*>(&Bs[k][0])[tx];
            unsigned long long b01 = pack2(bv.x, bv.y);
            unsigned long long b23 = pack2(bv.z, bv.w);
            float a[8] = {a0.x, a0.y, a0.z, a0.w, a1.x, a1.y, a1.z, a1.w};
#pragma unroll
            for (int i = 0; i < 8; ++i) {
                unsigned long long ai = pack2(a[i], a[i]);
                acc2[i][0] = ffma2(ai, b01, acc2[i][0]);
                acc2[i][1] = ffma2(ai, b23, acc2[i][1]);
            }
        }
        __syncthreads();
    }
#pragma unroll
    for (int i = 0; i < 8; ++i) {
        int gm = bm + ty * 8 + i;
        if (gm < NN) {
            float4 o;
            unpack2(acc2[i][0], o.x, o.y);
            unpack2(acc2[i][1], o.z, o.w);
            *reinterpret_cast<float4*>(g_h + (size_t)gm * HC + tx * 4) = o;
        }
    }
}

// ---------------- fused2: scan1 (warp-shuffle)  ||  attn_halves ---------------
// blocks [0, SCAN_NBLK)            : block-level inclusive scan of g_cnt
// blocks [SCAN_NBLK, +ATTNBLK)     : per-node attention halves (32 warps/block)
__global__ void fused2_kernel(const float* __restrict__ att_src,
                              const float* __restrict__ att_dst)
{
    if (blockIdx.x < SCAN_NBLK) {
        // ---- scan1 path: 1024 threads, warp-shuffle scan ----
        __shared__ int wsum[32];
        int t = threadIdx.x;
        int lane = t & 31;
        int wid = t >> 5;
        int i = blockIdx.x * 1024 + t;
        int v = (i < NN) ? g_cnt[i] : 0;
        int sc = v;
#pragma unroll
        for (int off = 1; off < 32; off <<= 1) {
            int n = __shfl_up_sync(0xFFFFFFFFu, sc, off);
            if (lane >= off) sc += n;
        }
        if (lane == 31) wsum[wid] = sc;
        __syncthreads();
        if (wid == 0) {
            int ws = wsum[lane];
#pragma unroll
            for (int off = 1; off < 32; off <<= 1) {
                int n = __shfl_up_sync(0xFFFFFFFFu, ws, off);
                if (lane >= off) ws += n;
            }
            wsum[lane] = ws;
        }
        __syncthreads();
        int base = (wid > 0) ? wsum[wid - 1] : 0;
        int inc = base + sc;
        if (i < NN) g_off[i + 1] = inc;
        if (t == 1023) g_bsum[blockIdx.x] = inc;
        return;
    }
    // ---- attn path ----
    int w = (blockIdx.x - SCAN_NBLK) * 32 + (threadIdx.x >> 5);
    int lane = threadIdx.x & 31;
    if (w >= NN) return;
    float4 hv = *reinterpret_cast<const float4*>(g_h + (size_t)w * HC + lane * 4);
    float4 s4 = *reinterpret_cast<const float4*>(att_src + lane * 4);
    float4 d4 = *reinterpret_cast<const float4*>(att_dst + lane * 4);
    float ps = hv.x * s4.x + hv.y * s4.y + hv.z * s4.z + hv.w * s4.w;
    float pd = hv.x * d4.x + hv.y * d4.y + hv.z * d4.z + hv.w * d4.w;
#pragma unroll
    for (int off = 1; off < 8; off <<= 1) {
        ps += __shfl_xor_sync(0xFFFFFFFFu, ps, off);
        pd += __shfl_xor_sync(0xFFFFFFFFu, pd, off);
    }
    float4 po, qo;
    po.x = __shfl_sync(0xFFFFFFFFu, ps, 0);
    po.y = __shfl_sync(0xFFFFFFFFu, ps, 8);
    po.z = __shfl_sync(0xFFFFFFFFu, ps, 16);
    po.w = __shfl_sync(0xFFFFFFFFu, ps, 24);
    qo.x = __shfl_sync(0xFFFFFFFFu, pd, 0);
    qo.y = __shfl_sync(0xFFFFFFFFu, pd, 8);
    qo.z = __shfl_sync(0xFFFFFFFFu, pd, 16);
    qo.w = __shfl_sync(0xFFFFFFFFu, pd, 24);
    if (lane == 0) {
        *reinterpret_cast<float4*>(g_asrc + w * 4) = po;
        *reinterpret_cast<float4*>(g_adst + w * 4) = qo;
    }
}

// ---------------- scan3: add cross-block prefix (scan2 folded in) ------------
__global__ void scan3_kernel()
{
    __shared__ int s_pref;
    if (threadIdx.x == 0) {
        int acc = 0;
        for (int b = 0; b < (int)blockIdx.x; ++b) acc += g_bsum[b];
        s_pref = acc;
    }
    __syncthreads();
    int i = blockIdx.x * 1024 + threadIdx.x;
    if (i < NN) g_off[i + 1] += s_pref;
    if (i == 0) g_off[0] = 0;
}

// ---------------- scatter: count-down slot assignment -------------------------
__global__ void scatter_kernel(const void* __restrict__ ei)
{
    int is64 = block_detect_is64((const int*)ei);
    int e = blockIdx.x * 256 + threadIdx.x;
    if (e < EE) {
        int d = load_edge(ei, (size_t)EE + e, is64);
        int s = load_edge(ei, (size_t)e, is64);
        if ((unsigned)d < NN && (unsigned)s < NN) {
            int rem = atomicSub(&g_cnt[d], 1);          // old count
            int pos = g_off[d] + rem - 1;
            if ((unsigned)pos < EE) g_srcsorted[pos] = s;
        }
    }
}

// ---------------- aggregation: warp per dst node -----------------------------
// Softmax without max-shift (logits bounded, shift-invariant => exact).
// Logit role:     lane = j*4 + kl  (j = edge slot 0..7, kl = head)
// Accumulate role: lane owns channels lane*4..lane*4+3, head kh = lane>>3
__global__ void agg_kernel(const float* __restrict__ bias)
{
    int w = (blockIdx.x * blockDim.x + threadIdx.x) >> 5;
    int lane = threadIdx.x & 31;
    if (w >= NN) return;
    const int kl = lane & 3;
    const int j  = lane >> 2;
    const int kh = lane >> 3;

    float adv_l = g_adst[w * 4 + kl];
    float asl_l = g_asrc[w * 4 + kl];
    float adv_a = g_adst[w * 4 + kh];
    float asl_a = g_asrc[w * 4 + kh];

    // self-loop contribution
    float e0l = asl_l + adv_l;
    e0l = (e0l > 0.f) ? e0l : NEG_SLOPE * e0l;
    float dnm = (j == 0) ? __expf(e0l) : 0.f;

    float e0a = asl_a + adv_a;
    e0a = (e0a > 0.f) ? e0a : NEG_SLOPE * e0a;
    float pe0a = __expf(e0a);
    float4 hw = *reinterpret_cast<const float4*>(g_h + (size_t)w * HC + lane * 4);
    float4 acc;
    acc.x = pe0a * hw.x; acc.y = pe0a * hw.y;
    acc.z = pe0a * hw.z; acc.w = pe0a * hw.w;

    const int beg = g_off[w];
    const int end = g_off[w + 1];
    int p = beg;
    for (; p + 8 <= end; p += 8) {
        int s = g_srcsorted[p + j];
        float as = __ldg(g_asrc + (size_t)s * 4 + kl);
        float e = as + adv_l;
        e = (e > 0.f) ? e : NEG_SLOPE * e;
        float pe = __expf(e);
        dnm += pe;
#pragma unroll
        for (int jj = 0; jj < 8; ++jj) {
            int   sj = __shfl_sync(0xFFFFFFFFu, s,  jj * 4);
            float q  = __shfl_sync(0xFFFFFFFFu, pe, jj * 4 + kh);
            float4 hv = __ldg(reinterpret_cast<const float4*>(g_h + (size_t)sj * HC) + lane);
            acc.x = fmaf(q, hv.x, acc.x);
            acc.y = fmaf(q, hv.y, acc.y);
            acc.z = fmaf(q, hv.z, acc.z);
            acc.w = fmaf(q, hv.w, acc.w);
        }
    }
    if (p < end) {
        int cnt = end - p;
        int ridx = p + ((j < cnt) ? j : (cnt - 1));
        int s = g_srcsorted[ridx];
        float as = __ldg(g_asrc + (size_t)s * 4 + kl);
        float e = as + adv_l;
        e = (e > 0.f) ? e : NEG_SLOPE * e;
        float pe = (j < cnt) ? __expf(e) : 0.f;
        dnm += pe;
        for (int jj = 0; jj < cnt; ++jj) {
            int   sj = __shfl_sync(0xFFFFFFFFu, s,  jj * 4);
            float q  = __shfl_sync(0xFFFFFFFFu, pe, jj * 4 + kh);
            float4 hv = __ldg(reinterpret_cast<const float4*>(g_h + (size_t)sj * HC) + lane);
            acc.x = fmaf(q, hv.x, acc.x);
            acc.y = fmaf(q, hv.y, acc.y);
            acc.z = fmaf(q, hv.z, acc.z);
            acc.w = fmaf(q, hv.w, acc.w);
        }
    }

    // reduce dnm over the 8 edge slots; lane l then holds denom for head (l&3)
    dnm += __shfl_xor_sync(0xFFFFFFFFu, dnm, 4);
    dnm += __shfl_xor_sync(0xFFFFFFFFu, dnm, 8);
    dnm += __shfl_xor_sync(0xFFFFFFFFu, dnm, 16);
    float dn = __shfl_sync(0xFFFFFFFFu, dnm, kh);
    float inv = 1.f / dn;

    float4 bb = *reinterpret_cast<const float4*>(bias + lane * 4);
    float4 r;
    r.x = acc.x * inv + bb.x;
    r.y = acc.y * inv + bb.y;
    r.z = acc.z * inv + bb.z;
    r.w = acc.w * inv + bb.w;
    r.x = (r.x > 0.f) ? r.x : (__expf(r.x) - 1.f);
    r.y = (r.y > 0.f) ? r.y : (__expf(r.y) - 1.f);
    r.z = (r.z > 0.f) ? r.z : (__expf(r.z) - 1.f);
    r.w = (r.w > 0.f) ? r.w : (__expf(r.w) - 1.f);
    *reinterpret_cast<float4*>(g_z + (size_t)w * HC + lane * 4) = r;
}

// ---------------- GEMM2: out = z @ lin_W + lin_b  (50000x128 * 128x64) -------
__global__ void gemm2_kernel(const float* __restrict__ linW,
                             const float* __restrict__ linb,
                             float* __restrict__ out)
{
    __shared__ float As[32][64];    // [k][m]
    __shared__ float Bs[32][64];    // [k][n]
    const int tid = threadIdx.x;
    const int tx = tid & 15;
    const int ty = tid >> 4;
    const int bm = blockIdx.x * 64;

    unsigned long long acc2[4][2];
#pragma unroll
    for (int i = 0; i < 4; ++i) { acc2[i][0] = 0ull; acc2[i][1] = 0ull; }

    for (int k0 = 0; k0 < HC; k0 += 32) {
#pragma unroll
        for (int r = 0; r < 2; ++r) {
            int idx = tid + r * 256;
            int row = idx >> 3;
            int kk4 = idx & 7;
            int gm = bm + row;
            float4 v = make_float4(0.f, 0.f, 0.f, 0.f);
            if (gm < NN)
                v = *reinterpret_cast<const float4*>(g_z + (size_t)gm * HC + k0 + kk4 * 4);
            As[kk4 * 4 + 0][row] = v.x;
            As[kk4 * 4 + 1][row] = v.y;
            As[kk4 * 4 + 2][row] = v.z;
            As[kk4 * 4 + 3][row] = v.w;
        }
#pragma unroll
        for (int r = 0; r < 2; ++r) {
            int idx = tid + r * 256;
            int kk = idx >> 4;
            int nn4 = idx & 15;
            *reinterpret_cast<float4*>(&Bs[kk][nn4 * 4]) =
                *reinterpret_cast<const float4*>(linW + (size_t)(k0 + kk) * OUT_DIM + nn4 * 4);
        }
        __syncthreads();
#pragma unroll
        for (int k = 0; k < 32; ++k) {
            float4 av = reinterpret_cast<const float4*>(&As[k][0])[ty];
            float4 bv = reinterpret_cast<const float4*>(&Bs[k][0])[tx];
            unsigned long long b01 = pack2(bv.x, bv.y);
            unsigned long long b23 = pack2(bv.z, bv.w);
            float a[4] = {av.x, av.y, av.z, av.w};
#pragma unroll
            for (int i = 0; i < 4; ++i) {
                unsigned long long ai = pack2(a[i], a[i]);
                acc2[i][0] = ffma2(ai, b01, acc2[i][0]);
                acc2[i][1] = ffma2(ai, b23, acc2[i][1]);
            }
        }
        __syncthreads();
    }
    float4 bb = *reinterpret_cast<const float4*>(linb + tx * 4);
#pragma unroll
    for (int i = 0; i < 4; ++i) {
        int gm = bm + ty * 4 + i;
        if (gm < NN) {
            float4 o;
            unpack2(acc2[i][0], o.x, o.y);
            unpack2(acc2[i][1], o.z, o.w);
            o.x += bb.x; o.y += bb.y; o.z += bb.z; o.w += bb.w;
            *reinterpret_cast<float4*>(out + (size_t)gm * OUT_DIM + tx * 4) = o;
        }
    }
}

// ---------------- launch ------------------------------------------------------
extern "C" void kernel_launch(void* const* d_in, const int* in_sizes, int n_in,
                              void* d_out, int out_size)
{
    const float* x        = (const float*)d_in[0];
    const void*  ei       = (const void*)d_in[1];
    const float* W        = (const float*)d_in[2];
    const float* att_src  = (const float*)d_in[3];
    const float* att_dst  = (const float*)d_in[4];
    const float* bias     = (const float*)d_in[5];
    const float* lin_W    = (const float*)d_in[6];
    const float* lin_b    = (const float*)d_in[7];
    float* out            = (float*)d_out;

    const int warp_blocks = (NN * 32 + 255) / 256;   // 6250
    const int edge_blocks = (EE + 255) / 256;        // 6250
    const int gemm_blocks = (NN + 63) / 64;          // 782

    void* cnt_ptr = nullptr;
    cudaGetSymbolAddress(&cnt_ptr, g_cnt);

    cudaMemsetAsync(cnt_ptr, 0, NN * sizeof(int));                 // launch 0
    fused1_kernel<<<G1BLK + HISTBLK, 256>>>(x, W, ei);             // launch 1
    fused2_kernel<<<SCAN_NBLK + ATTNBLK, 1024>>>(att_src, att_dst);// launch 2
    scan3_kernel<<<SCAN_NBLK, 1024>>>();                           // launch 3
    scatter_kernel<<<edge_blocks, 256>>>(ei);                      // launch 4
    agg_kernel<<<warp_blocks, 256>>>(bias);                        // launch 5 -> ncu target
    gemm2_kernel<<<gemm_blocks, 256>>>(lin_W, lin_b, out);         // launch 6
}

// round 9
// speedup vs baseline: 1.5761x; 1.0705x over previous
#include <cuda_runtime.h>
#include <cuda_fp16.h>
#include <cstdint>

// Problem constants (fixed shapes)
#define NN 50000
#define EE 1600000
#define IN_DIM 256
#define HC 128          // H*C = 4*32
#define OUT_DIM 64
#define NEG_SLOPE 0.2f
#define SCAN_NBLK 49    // ceil(50000/1024)
#define G1BLK 782       // gemm1 blocks  (ceil(50000/64))
#define HISTBLK 6250    // hist blocks   (EE/256)
#define ATTNBLK 1563    // attn blocks   (ceil(50000/32) nodes @32 warps/blk)

// ---------------- scratch (__device__ globals; no allocation allowed) -------
__device__ float  g_h[(size_t)NN * HC];    // x @ W (fp32)
__device__ __half g_h16[(size_t)NN * HC];  // fp16 shadow for the gather path
__device__ float  g_asrc[NN * 4];
__device__ float  g_adst[NN * 4];
__device__ float  g_z[(size_t)NN * HC];    // elu(agg + bias)
__device__ int    g_cnt[NN];
__device__ int    g_off[NN + 1];
__device__ int    g_bsum[64];
__device__ int    g_srcsorted[EE];

// ---------------- f32x2 packed FMA helpers (sm_103a FFMA2) -------------------
__device__ __forceinline__ unsigned long long pack2(float lo, float hi)
{
    unsigned long long r;
    asm("mov.b64 %0, {%1, %2};" : "=l"(r) : "f"(lo), "f"(hi));
    return r;
}
__device__ __forceinline__ void unpack2(unsigned long long v, float& lo, float& hi)
{
    asm("mov.b64 {%0, %1}, %2;" : "=f"(lo), "=f"(hi) : "l"(v));
}
__device__ __forceinline__ unsigned long long ffma2(unsigned long long a,
                                                    unsigned long long b,
                                                    unsigned long long c)
{
    unsigned long long d;
    asm("fma.rn.f32x2 %0, %1, %2, %3;" : "=l"(d) : "l"(a), "l"(b), "l"(c));
    return d;
}

// ---------------- per-block edge dtype detection ------------------------------
// int64 little-endian values < 2^31: odd int32 words are all zero.
__device__ __forceinline__ int block_detect_is64(const int* __restrict__ ei32)
{
    int any = 0;
    if (threadIdx.x < 64) any = ei32[2 * threadIdx.x + 1];
    return __syncthreads_or(any) ? 0 : 1;
}

__device__ __forceinline__ int load_edge(const void* ei, size_t idx, int is64)
{
    if (is64) return (int)((const long long*)ei)[idx];
    return ((const int*)ei)[idx];
}

// ---------------- fused1: gemm1 tiles  ||  hist -------------------------------
__global__ void fused1_kernel(const float* __restrict__ x,
                              const float* __restrict__ W,
                              const void* __restrict__ ei)
{
    if (blockIdx.x >= G1BLK) {
        // ---- hist path ----
        int is64 = block_detect_is64((const int*)ei);
        int e = (blockIdx.x - G1BLK) * 256 + threadIdx.x;
        if (e < EE) {
            int d = load_edge(ei, (size_t)EE + e, is64);
            if ((unsigned)d < NN) atomicAdd(&g_cnt[d], 1);
        }
        return;
    }
    // ---- gemm1 path ----
    __shared__ float As[32][64];    // [k][m]
    __shared__ float Bs[32][128];   // [k][n]
    const int tid = threadIdx.x;
    const int tx = tid & 31;
    const int ty = tid >> 5;
    const int bm = blockIdx.x * 64;

    unsigned long long acc2[8][2];
#pragma unroll
    for (int i = 0; i < 8; ++i) { acc2[i][0] = 0ull; acc2[i][1] = 0ull; }

    for (int k0 = 0; k0 < IN_DIM; k0 += 32) {
#pragma unroll
        for (int r = 0; r < 2; ++r) {
            int idx = tid + r * 256;
            int row = idx >> 3;
            int kk4 = idx & 7;
            int gm = bm + row;
            float4 v = make_float4(0.f, 0.f, 0.f, 0.f);
            if (gm < NN)
                v = *reinterpret_cast<const float4*>(x + (size_t)gm * IN_DIM + k0 + kk4 * 4);
            As[kk4 * 4 + 0][row] = v.x;
            As[kk4 * 4 + 1][row] = v.y;
            As[kk4 * 4 + 2][row] = v.z;
            As[kk4 * 4 + 3][row] = v.w;
        }
#pragma unroll
        for (int r = 0; r < 4; ++r) {
            int idx = tid + r * 256;
            int kk = idx >> 5;
            int nn4 = idx & 31;
            *reinterpret_cast<float4*>(&Bs[kk][nn4 * 4]) =
                *reinterpret_cast<const float4*>(W + (size_t)(k0 + kk) * HC + nn4 * 4);
        }
        __syncthreads();
#pragma unroll
        for (int k = 0; k < 32; ++k) {
            float4 a0 = reinterpret_cast<const float4*>(&As[k][0])[ty * 2 + 0];
            float4 a1 = reinterpret_cast<const float4*>(&As[k][0])[ty * 2 + 1];
            float4 bv = reinterpret_cast<const float4*>(&Bs[k][0])[tx];
            unsigned long long b01 = pack2(bv.x, bv.y);
            unsigned long long b23 = pack2(bv.z, bv.w);
            float a[8] = {a0.x, a0.y, a0.z, a0.w, a1.x, a1.y, a1.z, a1.w};
#pragma unroll
            for (int i = 0; i < 8; ++i) {
                unsigned long long ai = pack2(a[i], a[i]);
                acc2[i][0] = ffma2(ai, b01, acc2[i][0]);
                acc2[i][1] = ffma2(ai, b23, acc2[i][1]);
            }
        }
        __syncthreads();
    }
#pragma unroll
    for (int i = 0; i < 8; ++i) {
        int gm = bm + ty * 8 + i;
        if (gm < NN) {
            float4 o;
            unpack2(acc2[i][0], o.x, o.y);
            unpack2(acc2[i][1], o.z, o.w);
            *reinterpret_cast<float4*>(g_h + (size_t)gm * HC + tx * 4) = o;
            // fp16 shadow for the gather path
            __half2 h01 = __floats2half2_rn(o.x, o.y);
            __half2 h23 = __floats2half2_rn(o.z, o.w);
            *reinterpret_cast<__half2*>(g_h16 + (size_t)gm * HC + tx * 4 + 0) = h01;
            *reinterpret_cast<__half2*>(g_h16 + (size_t)gm * HC + tx * 4 + 2) = h23;
        }
    }
}

// ---------------- fused2: scan1 (warp-shuffle)  ||  attn_halves ---------------
__global__ void fused2_kernel(const float* __restrict__ att_src,
                              const float* __restrict__ att_dst)
{
    if (blockIdx.x < SCAN_NBLK) {
        __shared__ int wsum[32];
        int t = threadIdx.x;
        int lane = t & 31;
        int wid = t >> 5;
        int i = blockIdx.x * 1024 + t;
        int v = (i < NN) ? g_cnt[i] : 0;
        int sc = v;
#pragma unroll
        for (int off = 1; off < 32; off <<= 1) {
            int n = __shfl_up_sync(0xFFFFFFFFu, sc, off);
            if (lane >= off) sc += n;
        }
        if (lane == 31) wsum[wid] = sc;
        __syncthreads();
        if (wid == 0) {
            int ws = wsum[lane];
#pragma unroll
            for (int off = 1; off < 32; off <<= 1) {
                int n = __shfl_up_sync(0xFFFFFFFFu, ws, off);
                if (lane >= off) ws += n;
            }
            wsum[lane] = ws;
        }
        __syncthreads();
        int base = (wid > 0) ? wsum[wid - 1] : 0;
        int inc = base + sc;
        if (i < NN) g_off[i + 1] = inc;
        if (t == 1023) g_bsum[blockIdx.x] = inc;
        return;
    }
    // ---- attn path ----
    int w = (blockIdx.x - SCAN_NBLK) * 32 + (threadIdx.x >> 5);
    int lane = threadIdx.x & 31;
    if (w >= NN) return;
    float4 hv = *reinterpret_cast<const float4*>(g_h + (size_t)w * HC + lane * 4);
    float4 s4 = *reinterpret_cast<const float4*>(att_src + lane * 4);
    float4 d4 = *reinterpret_cast<const float4*>(att_dst + lane * 4);
    float ps = hv.x * s4.x + hv.y * s4.y + hv.z * s4.z + hv.w * s4.w;
    float pd = hv.x * d4.x + hv.y * d4.y + hv.z * d4.z + hv.w * d4.w;
#pragma unroll
    for (int off = 1; off < 8; off <<= 1) {
        ps += __shfl_xor_sync(0xFFFFFFFFu, ps, off);
        pd += __shfl_xor_sync(0xFFFFFFFFu, pd, off);
    }
    float4 po, qo;
    po.x = __shfl_sync(0xFFFFFFFFu, ps, 0);
    po.y = __shfl_sync(0xFFFFFFFFu, ps, 8);
    po.z = __shfl_sync(0xFFFFFFFFu, ps, 16);
    po.w = __shfl_sync(0xFFFFFFFFu, ps, 24);
    qo.x = __shfl_sync(0xFFFFFFFFu, pd, 0);
    qo.y = __shfl_sync(0xFFFFFFFFu, pd, 8);
    qo.z = __shfl_sync(0xFFFFFFFFu, pd, 16);
    qo.w = __shfl_sync(0xFFFFFFFFu, pd, 24);
    if (lane == 0) {
        *reinterpret_cast<float4*>(g_asrc + w * 4) = po;
        *reinterpret_cast<float4*>(g_adst + w * 4) = qo;
    }
}

// ---------------- scan3: add cross-block prefix -------------------------------
__global__ void scan3_kernel()
{
    __shared__ int s_pref;
    if (threadIdx.x == 0) {
        int acc = 0;
        for (int b = 0; b < (int)blockIdx.x; ++b) acc += g_bsum[b];
        s_pref = acc;
    }
    __syncthreads();
    int i = blockIdx.x * 1024 + threadIdx.x;
    if (i < NN) g_off[i + 1] += s_pref;
    if (i == 0) g_off[0] = 0;
}

// ---------------- scatter: count-down slot assignment -------------------------
__global__ void scatter_kernel(const void* __restrict__ ei)
{
    int is64 = block_detect_is64((const int*)ei);
    int e = blockIdx.x * 256 + threadIdx.x;
    if (e < EE) {
        int d = load_edge(ei, (size_t)EE + e, is64);
        int s = load_edge(ei, (size_t)e, is64);
        if ((unsigned)d < NN && (unsigned)s < NN) {
            int rem = atomicSub(&g_cnt[d], 1);          // old count
            int pos = g_off[d] + rem - 1;
            if ((unsigned)pos < EE) g_srcsorted[pos] = s;
        }
    }
}

// ---------------- aggregation: warp per dst node -----------------------------
// Softmax without max-shift (logits bounded, shift-invariant => exact).
// Logit role:     lane = j*4 + kl  (j = edge slot 0..7, kl = head)
// Accumulate role: lane owns channels lane*4..lane*4+3, head kh = lane>>3
// Neighbor features gathered in fp16 (8 B/lane); accumulators fp32.
__global__ void agg_kernel(const float* __restrict__ bias)
{
    int w = (blockIdx.x * blockDim.x + threadIdx.x) >> 5;
    int lane = threadIdx.x & 31;
    if (w >= NN) return;
    const int kl = lane & 3;
    const int j  = lane >> 2;
    const int kh = lane >> 3;

    float adv_l = g_adst[w * 4 + kl];
    float asl_l = g_asrc[w * 4 + kl];
    float adv_a = g_adst[w * 4 + kh];
    float asl_a = g_asrc[w * 4 + kh];

    // self-loop contribution (fp32 h)
    float e0l = asl_l + adv_l;
    e0l = (e0l > 0.f) ? e0l : NEG_SLOPE * e0l;
    float dnm = (j == 0) ? __expf(e0l) : 0.f;

    float e0a = asl_a + adv_a;
    e0a = (e0a > 0.f) ? e0a : NEG_SLOPE * e0a;
    float pe0a = __expf(e0a);
    float4 hw = *reinterpret_cast<const float4*>(g_h + (size_t)w * HC + lane * 4);
    float4 acc;
    acc.x = pe0a * hw.x; acc.y = pe0a * hw.y;
    acc.z = pe0a * hw.z; acc.w = pe0a * hw.w;

    const int beg = g_off[w];
    const int end = g_off[w + 1];
    int p = beg;
    for (; p + 8 <= end; p += 8) {
        int s = g_srcsorted[p + j];
        float as = __ldg(g_asrc + (size_t)s * 4 + kl);
        float e = as + adv_l;
        e = (e > 0.f) ? e : NEG_SLOPE * e;
        float pe = __expf(e);
        dnm += pe;
#pragma unroll
        for (int jj = 0; jj < 8; ++jj) {
            int   sj = __shfl_sync(0xFFFFFFFFu, s,  jj * 4);
            float q  = __shfl_sync(0xFFFFFFFFu, pe, jj * 4 + kh);
            const __half2* hp = reinterpret_cast<const __half2*>(
                g_h16 + (size_t)sj * HC + lane * 4);
            __half2 h01 = __ldg(hp + 0);
            __half2 h23 = __ldg(hp + 1);
            float2 f01 = __half22float2(h01);
            float2 f23 = __half22float2(h23);
            acc.x = fmaf(q, f01.x, acc.x);
            acc.y = fmaf(q, f01.y, acc.y);
            acc.z = fmaf(q, f23.x, acc.z);
            acc.w = fmaf(q, f23.y, acc.w);
        }
    }
    if (p < end) {
        int cnt = end - p;
        int ridx = p + ((j < cnt) ? j : (cnt - 1));
        int s = g_srcsorted[ridx];
        float as = __ldg(g_asrc + (size_t)s * 4 + kl);
        float e = as + adv_l;
        e = (e > 0.f) ? e : NEG_SLOPE * e;
        float pe = (j < cnt) ? __expf(e) : 0.f;
        dnm += pe;
        for (int jj = 0; jj < cnt; ++jj) {
            int   sj = __shfl_sync(0xFFFFFFFFu, s,  jj * 4);
            float q  = __shfl_sync(0xFFFFFFFFu, pe, jj * 4 + kh);
            const __half2* hp = reinterpret_cast<const __half2*>(
                g_h16 + (size_t)sj * HC + lane * 4);
            __half2 h01 = __ldg(hp + 0);
            __half2 h23 = __ldg(hp + 1);
            float2 f01 = __half22float2(h01);
            float2 f23 = __half22float2(h23);
            acc.x = fmaf(q, f01.x, acc.x);
            acc.y = fmaf(q, f01.y, acc.y);
            acc.z = fmaf(q, f23.x, acc.z);
            acc.w = fmaf(q, f23.y, acc.w);
        }
    }

    // reduce dnm over the 8 edge slots; lane l then holds denom for head (l&3)
    dnm += __shfl_xor_sync(0xFFFFFFFFu, dnm, 4);
    dnm += __shfl_xor_sync(0xFFFFFFFFu, dnm, 8);
    dnm += __shfl_xor_sync(0xFFFFFFFFu, dnm, 16);
    float dn = __shfl_sync(0xFFFFFFFFu, dnm, kh);
    float inv = 1.f / dn;

    float4 bb = *reinterpret_cast<const float4*>(bias + lane * 4);
    float4 r;
    r.x = acc.x * inv + bb.x;
    r.y = acc.y * inv + bb.y;
    r.z = acc.z * inv + bb.z;
    r.w = acc.w * inv + bb.w;
    r.x = (r.x > 0.f) ? r.x : (__expf(r.x) - 1.f);
    r.y = (r.y > 0.f) ? r.y : (__expf(r.y) - 1.f);
    r.z = (r.z > 0.f) ? r.z : (__expf(r.z) - 1.f);
    r.w = (r.w > 0.f) ? r.w : (__expf(r.w) - 1.f);
    *reinterpret_cast<float4*>(g_z + (size_t)w * HC + lane * 4) = r;
}

// ---------------- GEMM2: out = z @ lin_W + lin_b  (50000x128 * 128x64) -------
__global__ void gemm2_kernel(const float* __restrict__ linW,
                             const float* __restrict__ linb,
                             float* __restrict__ out)
{
    __shared__ float As[32][64];    // [k][m]
    __shared__ float Bs[32][64];    // [k][n]
    const int tid = threadIdx.x;
    const int tx = tid & 15;
    const int ty = tid >> 4;
    const int bm = blockIdx.x * 64;

    unsigned long long acc2[4][2];
#pragma unroll
    for (int i = 0; i < 4; ++i) { acc2[i][0] = 0ull; acc2[i][1] = 0ull; }

    for (int k0 = 0; k0 < HC; k0 += 32) {
#pragma unroll
        for (int r = 0; r < 2; ++r) {
            int idx = tid + r * 256;
            int row = idx >> 3;
            int kk4 = idx & 7;
            int gm = bm + row;
            float4 v = make_float4(0.f, 0.f, 0.f, 0.f);
            if (gm < NN)
                v = *reinterpret_cast<const float4*>(g_z + (size_t)gm * HC + k0 + kk4 * 4);
            As[kk4 * 4 + 0][row] = v.x;
            As[kk4 * 4 + 1][row] = v.y;
            As[kk4 * 4 + 2][row] = v.z;
            As[kk4 * 4 + 3][row] = v.w;
        }
#pragma unroll
        for (int r = 0; r < 2; ++r) {
            int idx = tid + r * 256;
            int kk = idx >> 4;
            int nn4 = idx & 15;
            *reinterpret_cast<float4*>(&Bs[kk][nn4 * 4]) =
                *reinterpret_cast<const float4*>(linW + (size_t)(k0 + kk) * OUT_DIM + nn4 * 4);
        }
        __syncthreads();
#pragma unroll
        for (int k = 0; k < 32; ++k) {
            float4 av = reinterpret_cast<const float4*>(&As[k][0])[ty];
            float4 bv = reinterpret_cast<const float4*>(&Bs[k][0])[tx];
            unsigned long long b01 = pack2(bv.x, bv.y);
            unsigned long long b23 = pack2(bv.z, bv.w);
            float a[4] = {av.x, av.y, av.z, av.w};
#pragma unroll
            for (int i = 0; i < 4; ++i) {
                unsigned long long ai = pack2(a[i], a[i]);
                acc2[i][0] = ffma2(ai, b01, acc2[i][0]);
                acc2[i][1] = ffma2(ai, b23, acc2[i][1]);
            }
        }
        __syncthreads();
    }
    float4 bb = *reinterpret_cast<const float4*>(linb + tx * 4);
#pragma unroll
    for (int i = 0; i < 4; ++i) {
        int gm = bm + ty * 4 + i;
        if (gm < NN) {
            float4 o;
            unpack2(acc2[i][0], o.x, o.y);
            unpack2(acc2[i][1], o.z, o.w);
            o.x += bb.x; o.y += bb.y; o.z += bb.z; o.w += bb.w;
            *reinterpret_cast<float4*>(out + (size_t)gm * OUT_DIM + tx * 4) = o;
        }
    }
}

// ---------------- launch ------------------------------------------------------
extern "C" void kernel_launch(void* const* d_in, const int* in_sizes, int n_in,
                              void* d_out, int out_size)
{
    const float* x        = (const float*)d_in[0];
    const void*  ei       = (const void*)d_in[1];
    const float* W        = (const float*)d_in[2];
    const float* att_src  = (const float*)d_in[3];
    const float* att_dst  = (const float*)d_in[4];
    const float* bias     = (const float*)d_in[5];
    const float* lin_W    = (const float*)d_in[6];
    const float* lin_b    = (const float*)d_in[7];
    float* out            = (float*)d_out;

    const int warp_blocks = (NN * 32 + 255) / 256;   // 6250
    const int edge_blocks = (EE + 255) / 256;        // 6250
    const int gemm_blocks = (NN + 63) / 64;          // 782

    void* cnt_ptr = nullptr;
    cudaGetSymbolAddress(&cnt_ptr, g_cnt);

    cudaMemsetAsync(cnt_ptr, 0, NN * sizeof(int));                 // launch 0
    fused1_kernel<<<G1BLK + HISTBLK, 256>>>(x, W, ei);             // launch 1
    fused2_kernel<<<SCAN_NBLK + ATTNBLK, 1024>>>(att_src, att_dst);// launch 2
    scan3_kernel<<<SCAN_NBLK, 1024>>>();                           // launch 3
    scatter_kernel<<<edge_blocks, 256>>>(ei);                      // launch 4
    agg_kernel<<<warp_blocks, 256>>>(bias);                        // launch 5 -> ncu target
    gemm2_kernel<<<gemm_blocks, 256>>>(lin_W, lin_b, out);         // launch 6
}